// round 3
// baseline (speedup 1.0000x reference)
#include <cuda_runtime.h>
#include <math.h>

// Problem constants
#define Bb 16
#define Tt 16
#define Cc 64
#define HD 64
#define HW 1024
#define IMW 32
#define NT 128
#define SROW 36
#define PLANE (34*SROW)   // 1224 floats per padded plane

typedef unsigned long long ull;

// Scratch (device globals: no allocation allowed)
__device__ float g_h   [Bb*HD*HW];
__device__ float g_hode[Bb*HD*HW];
__device__ float g_rh  [Bb*HD*HW];
__device__ float g_u   [Bb*HD*HW];
__device__ float g_gx  [(size_t)Tt*Bb*2*HD*HW];   // x-part of gates conv (+bias)
__device__ float g_cx  [(size_t)Tt*Bb*HD*HW];     // x-part of cand conv (+bias)

// ---- packed f32x2 helpers ----
__device__ __forceinline__ ull pk2(float lo, float hi) {
    ull r; asm("mov.b64 %0, {%1, %2};" : "=l"(r) : "f"(lo), "f"(hi)); return r;
}
__device__ __forceinline__ ull fma2(ull a, ull b, ull c) {
    ull d; asm("fma.rn.f32x2 %0, %1, %2, %3;" : "=l"(d) : "l"(a), "l"(b), "l"(c)); return d;
}
__device__ __forceinline__ float lo2(ull v) { return __uint_as_float((unsigned)v); }
__device__ __forceinline__ float hi2(ull v) { return __uint_as_float((unsigned)(v >> 32)); }

// ---------------------------------------------------------------------------
// Core: 3x3 SAME conv over 64 input channels, one 32x32 image, NOC output
// channels per CTA, 8 pixels per thread (128 threads), f32x2 packed math.
// Weights staged duplicated-as-pairs: ws2[((oc*64+ci)*3+r)*4 + tap] = (w,w).
// Planes: 4 x 1224 floats, paired double buffer, zeroed 1-px borders.
// smem = NOC*768 ull + 4*PLANE floats.
// ---------------------------------------------------------------------------
template<int NOC>
__device__ __forceinline__ void conv_core64(
    const float* __restrict__ in,     // [64][1024]
    const float* __restrict__ wsrc,   // per-oc row stride = wstride9 floats
    int wstride9, int ocb,
    ull acc2[NOC][4])
{
    extern __shared__ float smem[];
    ull*   ws2 = reinterpret_cast<ull*>(smem);        // NOC*768 pairs
    float* pl  = smem + NOC*1536;                     // 4*PLANE floats
    const int tid = threadIdx.x;
    const int row = tid >> 2;          // 0..31
    const int xb  = (tid & 3) << 3;    // 0,8,16,24

    // Stage weights duplicated: slot layout (oc, ci, r, tap[4: 3 real + pad])
    for (int i = tid; i < NOC*768; i += NT) {
        const int pr_ = i & 3;
        const int r_  = (i >> 2) % 3;
        const int ci_ = (i / 12) & 63;
        const int oc_ = i / 768;
        float v = 0.f;
        if (pr_ < 3)
            v = wsrc[(size_t)(ocb*NOC + oc_)*wstride9 + ci_*9 + r_*3 + pr_];
        ws2[i] = pk2(v, v);
    }
    for (int i = tid; i < 4*PLANE; i += NT) pl[i] = 0.f;

    const int goff = row*IMW + xb;
    float4 n0a = *reinterpret_cast<const float4*>(in + goff);
    float4 n0b = *reinterpret_cast<const float4*>(in + goff + 4);
    float4 n1a = *reinterpret_cast<const float4*>(in + HW + goff);
    float4 n1b = *reinterpret_cast<const float4*>(in + HW + goff + 4);
    __syncthreads();   // weights + zeroed planes visible

    #pragma unroll 1
    for (int pr = 0; pr < 32; pr++) {
        float* b0 = pl + (pr & 1)*2*PLANE;
        float* b1 = b0 + PLANE;
        {
            float* d0 = b0 + (row + 1)*SROW + xb + 1;
            d0[0]=n0a.x; d0[1]=n0a.y; d0[2]=n0a.z; d0[3]=n0a.w;
            d0[4]=n0b.x; d0[5]=n0b.y; d0[6]=n0b.z; d0[7]=n0b.w;
            float* d1 = b1 + (row + 1)*SROW + xb + 1;
            d1[0]=n1a.x; d1[1]=n1a.y; d1[2]=n1a.z; d1[3]=n1a.w;
            d1[4]=n1b.x; d1[5]=n1b.y; d1[6]=n1b.z; d1[7]=n1b.w;
        }
        __syncthreads();
        if (pr < 31) {
            const float* g = in + (2*pr + 2)*HW + goff;
            n0a = *reinterpret_cast<const float4*>(g);
            n0b = *reinterpret_cast<const float4*>(g + 4);
            n1a = *reinterpret_cast<const float4*>(g + HW);
            n1b = *reinterpret_cast<const float4*>(g + HW + 4);
        }
        #pragma unroll
        for (int half = 0; half < 2; half++) {
            const float* cur = half ? b1 : b0;
            const int ci = 2*pr + half;
            #pragma unroll
            for (int r = 0; r < 3; r++) {
                // aligned 8B loads of the 10-float window (xb .. xb+9)
                const ull* s = reinterpret_cast<const ull*>(cur + (row + r)*SROW + xb);
                ull E0 = s[0], E1 = s[1], E2 = s[2], E3 = s[3], E4 = s[4];
                ull O0 = pk2(hi2(E0), lo2(E1));
                ull O1 = pk2(hi2(E1), lo2(E2));
                ull O2 = pk2(hi2(E2), lo2(E3));
                ull O3 = pk2(hi2(E3), lo2(E4));
                #pragma unroll
                for (int oc = 0; oc < NOC; oc++) {
                    const ull* wp = ws2 + ((size_t)(oc*64 + ci)*3 + r)*4;
                    ulonglong2 w01 = *reinterpret_cast<const ulonglong2*>(wp);
                    ull w2p = wp[2];
                    acc2[oc][0] = fma2(E0, w01.x, fma2(O0, w01.y, fma2(E1, w2p, acc2[oc][0])));
                    acc2[oc][1] = fma2(E1, w01.x, fma2(O1, w01.y, fma2(E2, w2p, acc2[oc][1])));
                    acc2[oc][2] = fma2(E2, w01.x, fma2(O2, w01.y, fma2(E3, w2p, acc2[oc][2])));
                    acc2[oc][3] = fma2(E3, w01.x, fma2(O3, w01.y, fma2(E4, w2p, acc2[oc][3])));
                }
            }
        }
    }
}

__device__ __forceinline__ float sigmoidf_(float x) { return 1.f / (1.f + expf(-x)); }

__device__ __forceinline__ void st8(float* o, const float a[8]) {
    *reinterpret_cast<float4*>(o)     = make_float4(a[0],a[1],a[2],a[3]);
    *reinterpret_cast<float4*>(o + 4) = make_float4(a[4],a[5],a[6],a[7]);
}
__device__ __forceinline__ void unpack8(const ull p[4], float a[8]) {
    #pragma unroll
    for (int j = 0; j < 4; j++) { a[2*j] = lo2(p[j]); a[2*j+1] = hi2(p[j]); }
}

// ---------------------------------------------------------------------------
// Precompute x-contributions: out[t][b][co][pix] = conv(x_{T-1-t}) + bias
// grid = (cout/4, T*B), NOC=4
// ---------------------------------------------------------------------------
__global__ void __launch_bounds__(NT, 5) k_pre(
    const float* __restrict__ x0, const float* __restrict__ w, int wstride9,
    const float* __restrict__ bias, float* __restrict__ out, int cout)
{
    const int ocb = blockIdx.x, z = blockIdx.y;
    const int t = z >> 4, b = z & 15;
    const float* in = x0 + ((size_t)(b*Tt + (Tt-1-t))*Cc)*HW;

    ull acc2[4][4];
    #pragma unroll
    for (int oc = 0; oc < 4; oc++) {
        ull bv = pk2(bias[ocb*4 + oc], bias[ocb*4 + oc]);
        #pragma unroll
        for (int j = 0; j < 4; j++) acc2[oc][j] = bv;
    }
    conv_core64<4>(in, w, wstride9, ocb, acc2);

    const int row = threadIdx.x >> 2, xb = (threadIdx.x & 3) << 3;
    float* o = out + ((size_t)(t*Bb + b)*cout + ocb*4)*HW + row*IMW + xb;
    #pragma unroll
    for (int oc = 0; oc < 4; oc++) {
        float a[8]; unpack8(acc2[oc], a);
        st8(o + oc*HW, a);
    }
}

// ---------------------------------------------------------------------------
// ODE: h_ode = h + tanh(conv(h)+b)*dt   grid = (32, B), NOC=2
// ---------------------------------------------------------------------------
__global__ void __launch_bounds__(NT, 6) k_ode(
    const float* __restrict__ w, const float* __restrict__ bias,
    const float* __restrict__ ts, int step)
{
    const int ocb = blockIdx.x, b = blockIdx.y;
    const float* in = g_h + (size_t)b*HD*HW;

    ull acc2[2][4];
    #pragma unroll
    for (int oc = 0; oc < 2; oc++) {
        ull bv = pk2(bias[ocb*2 + oc], bias[ocb*2 + oc]);
        #pragma unroll
        for (int j = 0; j < 4; j++) acc2[oc][j] = bv;
    }
    conv_core64<2>(in, w, 576, ocb, acc2);

    const float dt = (step == 0) ? -0.01f : (ts[Tt-1-step] - ts[Tt-step]);
    const int row = threadIdx.x >> 2, xb = (threadIdx.x & 3) << 3;
    #pragma unroll
    for (int oc = 0; oc < 2; oc++) {
        size_t ib = ((size_t)b*HD + ocb*2 + oc)*HW + row*IMW + xb;
        float a[8]; unpack8(acc2[oc], a);
        float r[8];
        #pragma unroll
        for (int px = 0; px < 8; px++)
            r[px] = g_h[ib + px] + tanhf(a[px])*dt;
        st8(&g_hode[ib], r);
    }
}

// ---------------------------------------------------------------------------
// Gates: g = sigmoid(conv(h_ode)+gx).  co<64 -> rh = g*h_ode; else u = g.
// grid = (64, B), NOC=2
// ---------------------------------------------------------------------------
__global__ void __launch_bounds__(NT, 6) k_gates(const float* __restrict__ w, int step)
{
    const int ocb = blockIdx.x, b = blockIdx.y;
    const float* in = g_hode + (size_t)b*HD*HW;

    ull acc2[2][4];
    #pragma unroll
    for (int oc = 0; oc < 2; oc++)
        #pragma unroll
        for (int j = 0; j < 4; j++) acc2[oc][j] = 0ull;
    conv_core64<2>(in, w, 1152, ocb, acc2);

    const int row = threadIdx.x >> 2, xb = (threadIdx.x & 3) << 3;
    const int co0 = ocb*2;
    const float* pre = g_gx + ((size_t)(step*Bb + b)*(2*HD) + co0)*HW + row*IMW + xb;
    #pragma unroll
    for (int oc = 0; oc < 2; oc++) {
        float a[8]; unpack8(acc2[oc], a);
        float g[8];
        #pragma unroll
        for (int px = 0; px < 8; px++)
            g[px] = sigmoidf_(a[px] + pre[oc*HW + px]);
        if (co0 < HD) {
            size_t ib = ((size_t)b*HD + co0 + oc)*HW + row*IMW + xb;
            #pragma unroll
            for (int px = 0; px < 8; px++) g[px] *= g_hode[ib + px];
            st8(&g_rh[ib], g);
        } else {
            size_t ib = ((size_t)b*HD + co0 - HD + oc)*HW + row*IMW + xb;
            st8(&g_u[ib], g);
        }
    }
}

// ---------------------------------------------------------------------------
// Candidate + GRU update + mask. grid = (32, B), NOC=2
// ---------------------------------------------------------------------------
__global__ void __launch_bounds__(NT, 6) k_cand(
    const float* __restrict__ w, const float* __restrict__ mask, int step)
{
    const int ocb = blockIdx.x, b = blockIdx.y;
    const float* in = g_rh + (size_t)b*HD*HW;

    ull acc2[2][4];
    #pragma unroll
    for (int oc = 0; oc < 2; oc++)
        #pragma unroll
        for (int j = 0; j < 4; j++) acc2[oc][j] = 0ull;
    conv_core64<2>(in, w, 1152, ocb, acc2);

    const float m = mask[b*Tt + (Tt-1-step)];
    const int row = threadIdx.x >> 2, xb = (threadIdx.x & 3) << 3;
    const float* pre = g_cx + ((size_t)(step*Bb + b)*HD + ocb*2)*HW + row*IMW + xb;
    #pragma unroll
    for (int oc = 0; oc < 2; oc++) {
        size_t ib = ((size_t)b*HD + ocb*2 + oc)*HW + row*IMW + xb;
        float a[8]; unpack8(acc2[oc], a);
        float r[8];
        #pragma unroll
        for (int px = 0; px < 8; px++) {
            float ho = g_hode[ib + px];
            float c  = tanhf(a[px] + pre[oc*HW + px]);
            r[px] = ho + m*g_u[ib + px]*(c - ho);
        }
        st8(&g_h[ib], r);
    }
}

// ---------------------------------------------------------------------------
// Head: z1 = relu(W1 h + b1); z2 = W2 z1 + b2; out = [z2[:64] ; |z2[64:]|]
// grid = (4, B)
// ---------------------------------------------------------------------------
__global__ void __launch_bounds__(256) k_final(
    const float* __restrict__ w1, const float* __restrict__ b1,
    const float* __restrict__ w2, const float* __restrict__ b2,
    float* __restrict__ out)
{
    extern __shared__ float smem[];
    float* w1s = smem;          // [64][64]
    float* w2s = smem + 4096;   // [128][64]
    const int tid = threadIdx.x, pb = blockIdx.x, b = blockIdx.y;
    for (int i = tid; i < 4096; i += 256) w1s[i] = w1[i];
    for (int i = tid; i < 8192; i += 256) w2s[i] = w2[i];
    __syncthreads();

    const int pix = pb*256 + tid;
    float z1[64];
    #pragma unroll
    for (int co = 0; co < 64; co++) z1[co] = b1[co];
    for (int ci = 0; ci < 64; ci++) {
        float hv = g_h[((size_t)b*HD + ci)*HW + pix];
        #pragma unroll
        for (int co = 0; co < 64; co++) z1[co] += w1s[co*64 + ci]*hv;
    }
    #pragma unroll
    for (int co = 0; co < 64; co++) z1[co] = fmaxf(z1[co], 0.f);

    for (int co2 = 0; co2 < 128; co2++) {
        float a = b2[co2];
        #pragma unroll
        for (int ci = 0; ci < 64; ci++) a += w2s[co2*64 + ci]*z1[ci];
        if (co2 < 64)
            out[((size_t)b*HD + co2)*HW + pix] = a;
        else
            out[(size_t)Bb*HD*HW + ((size_t)b*HD + (co2 - 64))*HW + pix] = fabsf(a);
    }
}

// ---------------------------------------------------------------------------
extern "C" void kernel_launch(void* const* d_in, const int* in_sizes, int n_in,
                              void* d_out, int out_size)
{
    const float* input   = (const float*)d_in[0];
    const float* ts      = (const float*)d_in[1];
    const float* mask    = (const float*)d_in[2];
    const float* w_gates = (const float*)d_in[3];
    const float* b_gates = (const float*)d_in[4];
    const float* w_can   = (const float*)d_in[5];
    const float* b_can   = (const float*)d_in[6];
    const float* w_ode   = (const float*)d_in[7];
    const float* b_ode   = (const float*)d_in[8];
    const float* w_t1    = (const float*)d_in[9];
    const float* b_t1    = (const float*)d_in[10];
    const float* w_t2    = (const float*)d_in[11];
    const float* b_t2    = (const float*)d_in[12];
    float* out = (float*)d_out;

    float *hptr, *gxp, *cxp;
    cudaGetSymbolAddress((void**)&hptr, g_h);
    cudaGetSymbolAddress((void**)&gxp,  g_gx);
    cudaGetSymbolAddress((void**)&cxp,  g_cx);

    cudaMemsetAsync(hptr, 0, (size_t)Bb*HD*HW*sizeof(float));

    const int SM4 = 4*768*8 + 4*PLANE*4;   // 44160 B  (NOC=4)
    const int SM2 = 2*768*8 + 4*PLANE*4;   // 31872 B  (NOC=2)

    k_pre<<<dim3(32, Tt*Bb), NT, SM4>>>(input, w_gates, 1152, b_gates, gxp, 2*HD);
    k_pre<<<dim3(16, Tt*Bb), NT, SM4>>>(input, w_can,   1152, b_can,   cxp, HD);

    for (int s = 0; s < Tt; s++) {
        k_ode  <<<dim3(32, Bb), NT, SM2>>>(w_ode, b_ode, ts, s);
        k_gates<<<dim3(64, Bb), NT, SM2>>>(w_gates + 64*9, s);
        k_cand <<<dim3(32, Bb), NT, SM2>>>(w_can   + 64*9, mask, s);
    }

    k_final<<<dim3(4, Bb), 256, 12288*(int)sizeof(float)>>>(w_t1, b_t1, w_t2, b_t2, out);
}

// round 4
// speedup vs baseline: 1.0787x; 1.0787x over previous
#include <cuda_runtime.h>
#include <math.h>

// Problem constants
#define Bb 16
#define Tt 16
#define Cc 64
#define HD 64
#define HW 1024
#define IMW 32
#define NT 128
#define SROW 36
#define PLANE (34*SROW)   // 1224 floats per padded plane

// Scratch (device globals: no allocation allowed)
__device__ float g_h   [Bb*HD*HW];
__device__ float g_hode[Bb*HD*HW];
__device__ float g_rh  [Bb*HD*HW];
__device__ float g_u   [Bb*HD*HW];
__device__ float g_gx  [(size_t)Tt*Bb*2*HD*HW];   // x-part of gates conv (+bias)
__device__ float g_cx  [(size_t)Tt*Bb*HD*HW];     // x-part of cand conv (+bias)

// ---------------------------------------------------------------------------
// Core: 3x3 SAME conv over 64 input channels, one 32x32 image, NOC output
// channels per CTA, 8 pixels per thread (128 threads). Two input channels per
// barrier; 4 smem planes (paired double buffer) with zeroed 1-px borders.
// Weights padded to 12 floats per (oc,ci) so they load as 2xLDS.128 + 1 LDS
// (broadcast, conflict-free). smem = NOC*768 + 4*PLANE floats.
// ---------------------------------------------------------------------------
template<int NOC>
__device__ __forceinline__ void conv_core64(
    const float* __restrict__ in,     // [64][1024]
    const float* __restrict__ wsrc,   // per-oc row stride = wstride9 floats
    int wstride9, int ocb,
    float acc[NOC][8])
{
    extern __shared__ float smem[];
    float* ws = smem;                 // NOC*64*12 floats, 16B aligned rows
    float* pl = smem + NOC*768;       // 4*PLANE floats
    const int tid = threadIdx.x;
    const int row = tid >> 2;          // 0..31
    const int xb  = (tid & 3) << 3;    // 0,8,16,24

    // Stage weights: ws[(oc*64+ci)*12 + tap], taps 9..11 zero-padded
    for (int i = tid; i < NOC*768; i += NT) {
        const int tap = i % 12;
        const int ci_ = (i / 12) & 63;
        const int oc_ = i / 768;
        ws[i] = (tap < 9)
              ? wsrc[(size_t)(ocb*NOC + oc_)*wstride9 + ci_*9 + tap] : 0.f;
    }
    for (int i = tid; i < 4*PLANE; i += NT) pl[i] = 0.f;

    const int goff = row*IMW + xb;
    float4 n0a = *reinterpret_cast<const float4*>(in + goff);
    float4 n0b = *reinterpret_cast<const float4*>(in + goff + 4);
    float4 n1a = *reinterpret_cast<const float4*>(in + HW + goff);
    float4 n1b = *reinterpret_cast<const float4*>(in + HW + goff + 4);
    __syncthreads();   // zero/weights visible before interior stores

    #pragma unroll 1
    for (int pr = 0; pr < 32; pr++) {
        float* b0 = pl + (pr & 1)*2*PLANE;
        float* b1 = b0 + PLANE;
        {
            float* d0 = b0 + (row + 1)*SROW + xb + 1;
            d0[0]=n0a.x; d0[1]=n0a.y; d0[2]=n0a.z; d0[3]=n0a.w;
            d0[4]=n0b.x; d0[5]=n0b.y; d0[6]=n0b.z; d0[7]=n0b.w;
            float* d1 = b1 + (row + 1)*SROW + xb + 1;
            d1[0]=n1a.x; d1[1]=n1a.y; d1[2]=n1a.z; d1[3]=n1a.w;
            d1[4]=n1b.x; d1[5]=n1b.y; d1[6]=n1b.z; d1[7]=n1b.w;
        }
        __syncthreads();
        if (pr < 31) {
            const float* g = in + (2*pr + 2)*HW + goff;
            n0a = *reinterpret_cast<const float4*>(g);
            n0b = *reinterpret_cast<const float4*>(g + 4);
            n1a = *reinterpret_cast<const float4*>(g + HW);
            n1b = *reinterpret_cast<const float4*>(g + HW + 4);
        }
        #pragma unroll
        for (int half = 0; half < 2; half++) {
            const float* cur = half ? b1 : b0;
            const int ci = 2*pr + half;
            float p[3][10];
            #pragma unroll
            for (int r = 0; r < 3; r++) {
                const float* s = cur + (row + r)*SROW + xb;   // 16B aligned
                float4 a = *reinterpret_cast<const float4*>(s);
                float4 b = *reinterpret_cast<const float4*>(s + 4);
                float2 c = *reinterpret_cast<const float2*>(s + 8);
                p[r][0]=a.x; p[r][1]=a.y; p[r][2]=a.z; p[r][3]=a.w;
                p[r][4]=b.x; p[r][5]=b.y; p[r][6]=b.z; p[r][7]=b.w;
                p[r][8]=c.x; p[r][9]=c.y;
            }
            #pragma unroll
            for (int oc = 0; oc < NOC; oc++) {
                const float4* wp = reinterpret_cast<const float4*>(ws + (oc*64 + ci)*12);
                float4 wA = wp[0];
                float4 wB = wp[1];
                float  w8 = ws[(oc*64 + ci)*12 + 8];
                #pragma unroll
                for (int px = 0; px < 8; px++) {
                    acc[oc][px] += p[0][px]*wA.x + p[0][px+1]*wA.y + p[0][px+2]*wA.z
                                 + p[1][px]*wA.w + p[1][px+1]*wB.x + p[1][px+2]*wB.y
                                 + p[2][px]*wB.z + p[2][px+1]*wB.w + p[2][px+2]*w8;
                }
            }
        }
    }
}

__device__ __forceinline__ float sigmoidf_(float x) { return 1.f / (1.f + expf(-x)); }

__device__ __forceinline__ void st8(float* o, const float a[8]) {
    *reinterpret_cast<float4*>(o)     = make_float4(a[0],a[1],a[2],a[3]);
    *reinterpret_cast<float4*>(o + 4) = make_float4(a[4],a[5],a[6],a[7]);
}

// ---------------------------------------------------------------------------
// Precompute x-contributions: out[t][b][co][pix] = conv(x_{T-1-t}) + bias
// grid = (cout/4, T*B), NOC=4
// ---------------------------------------------------------------------------
__global__ void __launch_bounds__(NT) k_pre(
    const float* __restrict__ x0, const float* __restrict__ w, int wstride9,
    const float* __restrict__ bias, float* __restrict__ out, int cout)
{
    const int ocb = blockIdx.x, z = blockIdx.y;
    const int t = z >> 4, b = z & 15;
    const float* in = x0 + ((size_t)(b*Tt + (Tt-1-t))*Cc)*HW;

    float acc[4][8];
    #pragma unroll
    for (int oc = 0; oc < 4; oc++) {
        float bv = bias[ocb*4 + oc];
        #pragma unroll
        for (int px = 0; px < 8; px++) acc[oc][px] = bv;
    }
    conv_core64<4>(in, w, wstride9, ocb, acc);

    const int row = threadIdx.x >> 2, xb = (threadIdx.x & 3) << 3;
    float* o = out + ((size_t)(t*Bb + b)*cout + ocb*4)*HW + row*IMW + xb;
    #pragma unroll
    for (int oc = 0; oc < 4; oc++) st8(o + oc*HW, acc[oc]);
}

// ---------------------------------------------------------------------------
// ODE: h_ode = h + tanh(conv(h)+b)*dt   grid = (32, B), NOC=2
// ---------------------------------------------------------------------------
__global__ void __launch_bounds__(NT) k_ode(
    const float* __restrict__ w, const float* __restrict__ bias,
    const float* __restrict__ ts, int step)
{
    const int ocb = blockIdx.x, b = blockIdx.y;
    const float* in = g_h + (size_t)b*HD*HW;

    float acc[2][8];
    #pragma unroll
    for (int oc = 0; oc < 2; oc++) {
        float bv = bias[ocb*2 + oc];
        #pragma unroll
        for (int px = 0; px < 8; px++) acc[oc][px] = bv;
    }
    conv_core64<2>(in, w, 576, ocb, acc);

    const float dt = (step == 0) ? -0.01f : (ts[Tt-1-step] - ts[Tt-step]);
    const int row = threadIdx.x >> 2, xb = (threadIdx.x & 3) << 3;
    #pragma unroll
    for (int oc = 0; oc < 2; oc++) {
        size_t ib = ((size_t)b*HD + ocb*2 + oc)*HW + row*IMW + xb;
        float r[8];
        #pragma unroll
        for (int px = 0; px < 8; px++)
            r[px] = g_h[ib + px] + tanhf(acc[oc][px])*dt;
        st8(&g_hode[ib], r);
    }
}

// ---------------------------------------------------------------------------
// Gates: g = sigmoid(conv(h_ode)+gx).  co<64 -> rh = g*h_ode; else u = g.
// grid = (64, B), NOC=2
// ---------------------------------------------------------------------------
__global__ void __launch_bounds__(NT) k_gates(const float* __restrict__ w, int step)
{
    const int ocb = blockIdx.x, b = blockIdx.y;
    const float* in = g_hode + (size_t)b*HD*HW;

    float acc[2][8];
    #pragma unroll
    for (int oc = 0; oc < 2; oc++)
        #pragma unroll
        for (int px = 0; px < 8; px++) acc[oc][px] = 0.f;
    conv_core64<2>(in, w, 1152, ocb, acc);

    const int row = threadIdx.x >> 2, xb = (threadIdx.x & 3) << 3;
    const int co0 = ocb*2;
    const float* pre = g_gx + ((size_t)(step*Bb + b)*(2*HD) + co0)*HW + row*IMW + xb;
    #pragma unroll
    for (int oc = 0; oc < 2; oc++) {
        float g[8];
        #pragma unroll
        for (int px = 0; px < 8; px++)
            g[px] = sigmoidf_(acc[oc][px] + pre[oc*HW + px]);
        if (co0 < HD) {
            size_t ib = ((size_t)b*HD + co0 + oc)*HW + row*IMW + xb;
            #pragma unroll
            for (int px = 0; px < 8; px++) g[px] *= g_hode[ib + px];
            st8(&g_rh[ib], g);
        } else {
            size_t ib = ((size_t)b*HD + co0 - HD + oc)*HW + row*IMW + xb;
            st8(&g_u[ib], g);
        }
    }
}

// ---------------------------------------------------------------------------
// Candidate + GRU update + mask. grid = (32, B), NOC=2
// ---------------------------------------------------------------------------
__global__ void __launch_bounds__(NT) k_cand(
    const float* __restrict__ w, const float* __restrict__ mask, int step)
{
    const int ocb = blockIdx.x, b = blockIdx.y;
    const float* in = g_rh + (size_t)b*HD*HW;

    float acc[2][8];
    #pragma unroll
    for (int oc = 0; oc < 2; oc++)
        #pragma unroll
        for (int px = 0; px < 8; px++) acc[oc][px] = 0.f;
    conv_core64<2>(in, w, 1152, ocb, acc);

    const float m = mask[b*Tt + (Tt-1-step)];
    const int row = threadIdx.x >> 2, xb = (threadIdx.x & 3) << 3;
    const float* pre = g_cx + ((size_t)(step*Bb + b)*HD + ocb*2)*HW + row*IMW + xb;
    #pragma unroll
    for (int oc = 0; oc < 2; oc++) {
        size_t ib = ((size_t)b*HD + ocb*2 + oc)*HW + row*IMW + xb;
        float r[8];
        #pragma unroll
        for (int px = 0; px < 8; px++) {
            float ho = g_hode[ib + px];
            float c  = tanhf(acc[oc][px] + pre[oc*HW + px]);
            r[px] = ho + m*g_u[ib + px]*(c - ho);
        }
        st8(&g_h[ib], r);
    }
}

// ---------------------------------------------------------------------------
// Head: z1 = relu(W1 h + b1); z2 = W2 z1 + b2; out = [z2[:64] ; |z2[64:]|]
// grid = (4, B)
// ---------------------------------------------------------------------------
__global__ void __launch_bounds__(256) k_final(
    const float* __restrict__ w1, const float* __restrict__ b1,
    const float* __restrict__ w2, const float* __restrict__ b2,
    float* __restrict__ out)
{
    extern __shared__ float smem[];
    float* w1s = smem;          // [64][64]
    float* w2s = smem + 4096;   // [128][64]
    const int tid = threadIdx.x, pb = blockIdx.x, b = blockIdx.y;
    for (int i = tid; i < 4096; i += 256) w1s[i] = w1[i];
    for (int i = tid; i < 8192; i += 256) w2s[i] = w2[i];
    __syncthreads();

    const int pix = pb*256 + tid;
    float z1[64];
    #pragma unroll
    for (int co = 0; co < 64; co++) z1[co] = b1[co];
    for (int ci = 0; ci < 64; ci++) {
        float hv = g_h[((size_t)b*HD + ci)*HW + pix];
        #pragma unroll
        for (int co = 0; co < 64; co++) z1[co] += w1s[co*64 + ci]*hv;
    }
    #pragma unroll
    for (int co = 0; co < 64; co++) z1[co] = fmaxf(z1[co], 0.f);

    for (int co2 = 0; co2 < 128; co2++) {
        float a = b2[co2];
        #pragma unroll
        for (int ci = 0; ci < 64; ci++) a += w2s[co2*64 + ci]*z1[ci];
        if (co2 < 64)
            out[((size_t)b*HD + co2)*HW + pix] = a;
        else
            out[(size_t)Bb*HD*HW + ((size_t)b*HD + (co2 - 64))*HW + pix] = fabsf(a);
    }
}

// ---------------------------------------------------------------------------
extern "C" void kernel_launch(void* const* d_in, const int* in_sizes, int n_in,
                              void* d_out, int out_size)
{
    const float* input   = (const float*)d_in[0];
    const float* ts      = (const float*)d_in[1];
    const float* mask    = (const float*)d_in[2];
    const float* w_gates = (const float*)d_in[3];
    const float* b_gates = (const float*)d_in[4];
    const float* w_can   = (const float*)d_in[5];
    const float* b_can   = (const float*)d_in[6];
    const float* w_ode   = (const float*)d_in[7];
    const float* b_ode   = (const float*)d_in[8];
    const float* w_t1    = (const float*)d_in[9];
    const float* b_t1    = (const float*)d_in[10];
    const float* w_t2    = (const float*)d_in[11];
    const float* b_t2    = (const float*)d_in[12];
    float* out = (float*)d_out;

    float *hptr, *gxp, *cxp;
    cudaGetSymbolAddress((void**)&hptr, g_h);
    cudaGetSymbolAddress((void**)&gxp,  g_gx);
    cudaGetSymbolAddress((void**)&cxp,  g_cx);

    cudaMemsetAsync(hptr, 0, (size_t)Bb*HD*HW*sizeof(float));

    const int SM4 = (4*768 + 4*PLANE) * (int)sizeof(float);  // 31872 B
    const int SM2 = (2*768 + 4*PLANE) * (int)sizeof(float);  // 25728 B

    k_pre<<<dim3(32, Tt*Bb), NT, SM4>>>(input, w_gates, 1152, b_gates, gxp, 2*HD);
    k_pre<<<dim3(16, Tt*Bb), NT, SM4>>>(input, w_can,   1152, b_can,   cxp, HD);

    for (int s = 0; s < Tt; s++) {
        k_ode  <<<dim3(32, Bb), NT, SM2>>>(w_ode, b_ode, ts, s);
        k_gates<<<dim3(64, Bb), NT, SM2>>>(w_gates + 64*9, s);
        k_cand <<<dim3(32, Bb), NT, SM2>>>(w_can   + 64*9, mask, s);
    }

    k_final<<<dim3(4, Bb), 256, 12288*(int)sizeof(float)>>>(w_t1, b_t1, w_t2, b_t2, out);
}

// round 5
// speedup vs baseline: 1.2386x; 1.1482x over previous
#include <cuda_runtime.h>
#include <math.h>

// Problem constants
#define Bb 16
#define Tt 16
#define Cc 64
#define HD 64
#define HW 1024
#define IMW 32
#define NT 128
#define SROW 36
#define PLANE (34*SROW)   // 1224 floats per padded plane

// Scratch (device globals: no allocation allowed)
__device__ float g_h   [Bb*HD*HW];
__device__ float g_hode[Bb*HD*HW];
__device__ float g_rh  [Bb*HD*HW];
__device__ float g_u   [Bb*HD*HW];
__device__ float g_gx  [(size_t)Tt*Bb*2*HD*HW];   // x-part of gates conv (+bias)
__device__ float g_cx  [(size_t)Tt*Bb*HD*HW];     // x-part of cand conv (+bias)

// ---------------------------------------------------------------------------
// Core: 3x3 SAME conv over 64 input channels, one 32x32 image, 4 output
// channels per CTA, 8 pixels per thread (128 threads). Two input channels per
// barrier; 4 smem planes (paired double buffer) with zeroed 1-px borders.
// Weights padded to 12 floats per (oc,ci): 2xLDS.128 + 1 LDS, broadcast.
// smem = 4*768 + 4*PLANE floats = 31872 B.
// ---------------------------------------------------------------------------
__device__ __forceinline__ void conv_core64(
    const float* __restrict__ in,     // [64][1024]
    const float* __restrict__ wsrc,   // per-oc row stride = wstride9 floats
    int wstride9, int ocb,
    float acc[4][8])
{
    extern __shared__ float smem[];
    float* ws = smem;                 // 4*64*12 floats
    float* pl = smem + 4*768;         // 4*PLANE floats
    const int tid = threadIdx.x;
    const int row = tid >> 2;          // 0..31
    const int xb  = (tid & 3) << 3;    // 0,8,16,24

    // Stage weights: ws[(oc*64+ci)*12 + tap], taps 9..11 zero-padded
    for (int i = tid; i < 4*768; i += NT) {
        const int tap = i % 12;
        const int ci_ = (i / 12) & 63;
        const int oc_ = i / 768;
        ws[i] = (tap < 9)
              ? wsrc[(size_t)(ocb*4 + oc_)*wstride9 + ci_*9 + tap] : 0.f;
    }
    for (int i = tid; i < 4*PLANE; i += NT) pl[i] = 0.f;

    const int goff = row*IMW + xb;
    float4 n0a = *reinterpret_cast<const float4*>(in + goff);
    float4 n0b = *reinterpret_cast<const float4*>(in + goff + 4);
    float4 n1a = *reinterpret_cast<const float4*>(in + HW + goff);
    float4 n1b = *reinterpret_cast<const float4*>(in + HW + goff + 4);
    __syncthreads();   // zero/weights visible before interior stores

    #pragma unroll 1
    for (int pr = 0; pr < 32; pr++) {
        float* b0 = pl + (pr & 1)*2*PLANE;
        float* b1 = b0 + PLANE;
        {
            float* d0 = b0 + (row + 1)*SROW + xb + 1;
            d0[0]=n0a.x; d0[1]=n0a.y; d0[2]=n0a.z; d0[3]=n0a.w;
            d0[4]=n0b.x; d0[5]=n0b.y; d0[6]=n0b.z; d0[7]=n0b.w;
            float* d1 = b1 + (row + 1)*SROW + xb + 1;
            d1[0]=n1a.x; d1[1]=n1a.y; d1[2]=n1a.z; d1[3]=n1a.w;
            d1[4]=n1b.x; d1[5]=n1b.y; d1[6]=n1b.z; d1[7]=n1b.w;
        }
        __syncthreads();
        if (pr < 31) {
            const float* g = in + (2*pr + 2)*HW + goff;
            n0a = *reinterpret_cast<const float4*>(g);
            n0b = *reinterpret_cast<const float4*>(g + 4);
            n1a = *reinterpret_cast<const float4*>(g + HW);
            n1b = *reinterpret_cast<const float4*>(g + HW + 4);
        }
        #pragma unroll
        for (int half = 0; half < 2; half++) {
            const float* cur = half ? b1 : b0;
            const int ci = 2*pr + half;
            float p[3][10];
            #pragma unroll
            for (int r = 0; r < 3; r++) {
                const float* s = cur + (row + r)*SROW + xb;   // 16B aligned
                float4 a = *reinterpret_cast<const float4*>(s);
                float4 b = *reinterpret_cast<const float4*>(s + 4);
                float2 c = *reinterpret_cast<const float2*>(s + 8);
                p[r][0]=a.x; p[r][1]=a.y; p[r][2]=a.z; p[r][3]=a.w;
                p[r][4]=b.x; p[r][5]=b.y; p[r][6]=b.z; p[r][7]=b.w;
                p[r][8]=c.x; p[r][9]=c.y;
            }
            #pragma unroll
            for (int oc = 0; oc < 4; oc++) {
                const float4* wp = reinterpret_cast<const float4*>(ws + (oc*64 + ci)*12);
                float4 wA = wp[0];
                float4 wB = wp[1];
                float  w8 = ws[(oc*64 + ci)*12 + 8];
                #pragma unroll
                for (int px = 0; px < 8; px++) {
                    acc[oc][px] += p[0][px]*wA.x + p[0][px+1]*wA.y + p[0][px+2]*wA.z
                                 + p[1][px]*wA.w + p[1][px+1]*wB.x + p[1][px+2]*wB.y
                                 + p[2][px]*wB.z + p[2][px+1]*wB.w + p[2][px+2]*w8;
                }
            }
        }
    }
}

__device__ __forceinline__ float sigmoidf_(float x) { return 1.f / (1.f + expf(-x)); }

__device__ __forceinline__ void st8(float* o, const float a[8]) {
    *reinterpret_cast<float4*>(o)     = make_float4(a[0],a[1],a[2],a[3]);
    *reinterpret_cast<float4*>(o + 4) = make_float4(a[4],a[5],a[6],a[7]);
}

// ---------------------------------------------------------------------------
// Precompute x-contributions: out[t][b][co][pix] = conv(x_{T-1-t}) + bias
// grid = (cout/4, T*B)
// ---------------------------------------------------------------------------
__global__ void __launch_bounds__(NT) k_pre(
    const float* __restrict__ x0, const float* __restrict__ w, int wstride9,
    const float* __restrict__ bias, float* __restrict__ out, int cout)
{
    const int ocb = blockIdx.x, z = blockIdx.y;
    const int t = z >> 4, b = z & 15;
    const float* in = x0 + ((size_t)(b*Tt + (Tt-1-t))*Cc)*HW;

    float acc[4][8];
    #pragma unroll
    for (int oc = 0; oc < 4; oc++) {
        float bv = bias[ocb*4 + oc];
        #pragma unroll
        for (int px = 0; px < 8; px++) acc[oc][px] = bv;
    }
    conv_core64(in, w, wstride9, ocb, acc);

    const int row = threadIdx.x >> 2, xb = (threadIdx.x & 3) << 3;
    float* o = out + ((size_t)(t*Bb + b)*cout + ocb*4)*HW + row*IMW + xb;
    #pragma unroll
    for (int oc = 0; oc < 4; oc++) st8(o + oc*HW, acc[oc]);
}

// ---------------------------------------------------------------------------
// ODE: h_ode = h + tanh(conv(h)+b)*dt   grid = (16, B)
// ---------------------------------------------------------------------------
__global__ void __launch_bounds__(NT) k_ode(
    const float* __restrict__ w, const float* __restrict__ bias,
    const float* __restrict__ ts, int step)
{
    const int ocb = blockIdx.x, b = blockIdx.y;
    const float* in = g_h + (size_t)b*HD*HW;

    float acc[4][8];
    #pragma unroll
    for (int oc = 0; oc < 4; oc++) {
        float bv = bias[ocb*4 + oc];
        #pragma unroll
        for (int px = 0; px < 8; px++) acc[oc][px] = bv;
    }
    conv_core64(in, w, 576, ocb, acc);

    const float dt = (step == 0) ? -0.01f : (ts[Tt-1-step] - ts[Tt-step]);
    const int row = threadIdx.x >> 2, xb = (threadIdx.x & 3) << 3;
    #pragma unroll
    for (int oc = 0; oc < 4; oc++) {
        size_t ib = ((size_t)b*HD + ocb*4 + oc)*HW + row*IMW + xb;
        float r[8];
        #pragma unroll
        for (int px = 0; px < 8; px++)
            r[px] = g_h[ib + px] + tanhf(acc[oc][px])*dt;
        st8(&g_hode[ib], r);
    }
}

// ---------------------------------------------------------------------------
// Gates: g = sigmoid(conv(h_ode)+gx).  co<64 -> rh = g*h_ode; else u = g.
// grid = (32, B)
// ---------------------------------------------------------------------------
__global__ void __launch_bounds__(NT) k_gates(const float* __restrict__ w, int step)
{
    const int ocb = blockIdx.x, b = blockIdx.y;
    const float* in = g_hode + (size_t)b*HD*HW;

    float acc[4][8];
    #pragma unroll
    for (int oc = 0; oc < 4; oc++)
        #pragma unroll
        for (int px = 0; px < 8; px++) acc[oc][px] = 0.f;
    conv_core64(in, w, 1152, ocb, acc);

    const int row = threadIdx.x >> 2, xb = (threadIdx.x & 3) << 3;
    const int co0 = ocb*4;
    const float* pre = g_gx + ((size_t)(step*Bb + b)*(2*HD) + co0)*HW + row*IMW + xb;
    #pragma unroll
    for (int oc = 0; oc < 4; oc++) {
        float g[8];
        #pragma unroll
        for (int px = 0; px < 8; px++)
            g[px] = sigmoidf_(acc[oc][px] + pre[oc*HW + px]);
        if (co0 < HD) {
            size_t ib = ((size_t)b*HD + co0 + oc)*HW + row*IMW + xb;
            #pragma unroll
            for (int px = 0; px < 8; px++) g[px] *= g_hode[ib + px];
            st8(&g_rh[ib], g);
        } else {
            size_t ib = ((size_t)b*HD + co0 - HD + oc)*HW + row*IMW + xb;
            st8(&g_u[ib], g);
        }
    }
}

// ---------------------------------------------------------------------------
// Candidate + GRU update + mask. grid = (16, B)
// ---------------------------------------------------------------------------
__global__ void __launch_bounds__(NT) k_cand(
    const float* __restrict__ w, const float* __restrict__ mask, int step)
{
    const int ocb = blockIdx.x, b = blockIdx.y;
    const float* in = g_rh + (size_t)b*HD*HW;

    float acc[4][8];
    #pragma unroll
    for (int oc = 0; oc < 4; oc++)
        #pragma unroll
        for (int px = 0; px < 8; px++) acc[oc][px] = 0.f;
    conv_core64(in, w, 1152, ocb, acc);

    const float m = mask[b*Tt + (Tt-1-step)];
    const int row = threadIdx.x >> 2, xb = (threadIdx.x & 3) << 3;
    const float* pre = g_cx + ((size_t)(step*Bb + b)*HD + ocb*4)*HW + row*IMW + xb;
    #pragma unroll
    for (int oc = 0; oc < 4; oc++) {
        size_t ib = ((size_t)b*HD + ocb*4 + oc)*HW + row*IMW + xb;
        float r[8];
        #pragma unroll
        for (int px = 0; px < 8; px++) {
            float ho = g_hode[ib + px];
            float c  = tanhf(acc[oc][px] + pre[oc*HW + px]);
            r[px] = ho + m*g_u[ib + px]*(c - ho);
        }
        st8(&g_h[ib], r);
    }
}

// ---------------------------------------------------------------------------
// Head: z1 = relu(W1 h + b1); z2 = W2 z1 + b2; out = [z2[:64] ; |z2[64:]|]
// grid = (4, B)
// ---------------------------------------------------------------------------
__global__ void __launch_bounds__(256) k_final(
    const float* __restrict__ w1, const float* __restrict__ b1,
    const float* __restrict__ w2, const float* __restrict__ b2,
    float* __restrict__ out)
{
    extern __shared__ float smem[];
    float* w1s = smem;          // [64][64]
    float* w2s = smem + 4096;   // [128][64]
    const int tid = threadIdx.x, pb = blockIdx.x, b = blockIdx.y;
    for (int i = tid; i < 4096; i += 256) w1s[i] = w1[i];
    for (int i = tid; i < 8192; i += 256) w2s[i] = w2[i];
    __syncthreads();

    const int pix = pb*256 + tid;
    float z1[64];
    #pragma unroll
    for (int co = 0; co < 64; co++) z1[co] = b1[co];
    for (int ci = 0; ci < 64; ci++) {
        float hv = g_h[((size_t)b*HD + ci)*HW + pix];
        #pragma unroll
        for (int co = 0; co < 64; co++) z1[co] += w1s[co*64 + ci]*hv;
    }
    #pragma unroll
    for (int co = 0; co < 64; co++) z1[co] = fmaxf(z1[co], 0.f);

    for (int co2 = 0; co2 < 128; co2++) {
        float a = b2[co2];
        #pragma unroll
        for (int ci = 0; ci < 64; ci++) a += w2s[co2*64 + ci]*z1[ci];
        if (co2 < 64)
            out[((size_t)b*HD + co2)*HW + pix] = a;
        else
            out[(size_t)Bb*HD*HW + ((size_t)b*HD + (co2 - 64))*HW + pix] = fabsf(a);
    }
}

// ---------------------------------------------------------------------------
extern "C" void kernel_launch(void* const* d_in, const int* in_sizes, int n_in,
                              void* d_out, int out_size)
{
    const float* input   = (const float*)d_in[0];
    const float* ts      = (const float*)d_in[1];
    const float* mask    = (const float*)d_in[2];
    const float* w_gates = (const float*)d_in[3];
    const float* b_gates = (const float*)d_in[4];
    const float* w_can   = (const float*)d_in[5];
    const float* b_can   = (const float*)d_in[6];
    const float* w_ode   = (const float*)d_in[7];
    const float* b_ode   = (const float*)d_in[8];
    const float* w_t1    = (const float*)d_in[9];
    const float* b_t1    = (const float*)d_in[10];
    const float* w_t2    = (const float*)d_in[11];
    const float* b_t2    = (const float*)d_in[12];
    float* out = (float*)d_out;

    float *hptr, *gxp, *cxp;
    cudaGetSymbolAddress((void**)&hptr, g_h);
    cudaGetSymbolAddress((void**)&gxp,  g_gx);
    cudaGetSymbolAddress((void**)&cxp,  g_cx);

    cudaMemsetAsync(hptr, 0, (size_t)Bb*HD*HW*sizeof(float));

    const int CSM = (4*768 + 4*PLANE) * (int)sizeof(float);  // 31872 B

    k_pre<<<dim3(32, Tt*Bb), NT, CSM>>>(input, w_gates, 1152, b_gates, gxp, 2*HD);
    k_pre<<<dim3(16, Tt*Bb), NT, CSM>>>(input, w_can,   1152, b_can,   cxp, HD);

    for (int s = 0; s < Tt; s++) {
        k_ode  <<<dim3(16, Bb), NT, CSM>>>(w_ode, b_ode, ts, s);
        k_gates<<<dim3(32, Bb), NT, CSM>>>(w_gates + 64*9, s);
        k_cand <<<dim3(16, Bb), NT, CSM>>>(w_can   + 64*9, mask, s);
    }

    k_final<<<dim3(4, Bb), 256, 12288*(int)sizeof(float)>>>(w_t1, b_t1, w_t2, b_t2, out);
}